// round 7
// baseline (speedup 1.0000x reference)
#include <cuda_runtime.h>

// Problem dims (fixed per reference)
#define B_DIM 2
#define L_DIM 4096
#define DIN   512
#define H_DIM 8
#define DK    64
#define DV    64
#define DOUT  512

// ---------------- scratch (device globals; no allocation allowed) ----------
__device__ float g_G  [B_DIM * DIN * DIN];           // Gram x^T x, per batch (symmetric)
__device__ float g_P2t[B_DIM * H_DIM * DIN * DK];    // G @ W_k  (512 x 64 per b,h)
__device__ float g_Mt [B_DIM * H_DIM * DK * DK];     // (K^T V)^T (64 x 64 per b,h)
__device__ float g_R  [B_DIM * H_DIM * DK * DOUT];   // (K^T V) @ W_o (64 x 512 per b,h)
__device__ float g_WqF[DIN * H_DIM * DK];            // W_q gathered: [m][h*64+k]
__device__ float g_E  [B_DIM * DIN * DOUT];          // Sum_h Wq M Wo (512 x 512 per b)

// ---------------- helpers --------------------------------------------------
__global__ void zero_kernel(float* p, int n4) {
    int i = blockIdx.x * blockDim.x + threadIdx.x;
    if (i < n4) reinterpret_cast<float4*>(p)[i] = make_float4(0.f, 0.f, 0.f, 0.f);
}

// WqF[m][h*64+k] = Wq[h][m][k]
__global__ void rearrange_wq(const float* __restrict__ Wq, float* __restrict__ out) {
    int idx = blockIdx.x * blockDim.x + threadIdx.x;   // [0, 512*512)
    int m  = idx >> 9;
    int kg = idx & 511;
    int h  = kg >> 6;
    int k  = kg & 63;
    out[idx] = Wq[h * (DIN * DK) + m * DK + k];
}

// ---------------- big GEMM: 128x128 tile, 8x8 per thread, Kc=16 ------------
// TA=true : C[m,n] = sum_k A[k*lda+m] * B[k*ldb+n]   (A is K x M)
// TA=false: C[m,n] = sum_k A[m*lda+k] * B[k*ldb+n]   (A is M x K)
// blockIdx.z = batch*ksplit + slice; each slice reduces K/ksplit and
// (ATOMIC) atomically accumulates into C (C must be pre-zeroed).
template<bool TA, bool ATOMIC>
__global__ void __launch_bounds__(256, 2) gemm_big(
    const float* __restrict__ Ag, const float* __restrict__ Bg, float* __restrict__ Cg,
    int K, int lda, int ldb, int ldc,
    long sA, long sB, long sC, int ksplit)
{
    int z     = blockIdx.z;
    int batch = z / ksplit;
    int slice = z - batch * ksplit;
    int kLen  = K / ksplit;
    int k0    = slice * kLen;

    const float* A = Ag + (long)batch * sA;
    const float* B = Bg + (long)batch * sB;
    float*       C = Cg + (long)batch * sC;

    int m0 = blockIdx.y * 128;
    int n0 = blockIdx.x * 128;

    __shared__ float As[16][132];   // +4 pad: conflict-free NN scatter stores
    __shared__ float Bs[16][128];

    float acc[8][8];
    #pragma unroll
    for (int i = 0; i < 8; i++)
        #pragma unroll
        for (int j = 0; j < 8; j++) acc[i][j] = 0.f;

    int tid = threadIdx.x;          // 256 threads = 16x16
    int tx  = tid & 15;
    int ty  = tid >> 4;

    for (int kt = 0; kt < kLen; kt += 16) {
        // ---- load A tile into As[kk][m] ----
        if (TA) {
            #pragma unroll
            for (int i = 0; i < 2; i++) {
                int idx = tid + i * 256;           // 512 float4 total
                int kk  = idx >> 5;                // 32 float4 per k-row
                int mm  = (idx & 31) << 2;
                float4 v = *reinterpret_cast<const float4*>(
                    &A[(long)(k0 + kt + kk) * lda + m0 + mm]);
                *reinterpret_cast<float4*>(&As[kk][mm]) = v;
            }
        } else {
            #pragma unroll
            for (int i = 0; i < 2; i++) {
                int idx = tid + i * 256;           // 128 rows x 4 float4
                int mm  = idx >> 2;
                int kk  = (idx & 3) << 2;
                float4 v = *reinterpret_cast<const float4*>(
                    &A[(long)(m0 + mm) * lda + k0 + kt + kk]);
                As[kk + 0][mm] = v.x;
                As[kk + 1][mm] = v.y;
                As[kk + 2][mm] = v.z;
                As[kk + 3][mm] = v.w;
            }
        }
        // ---- load B tile into Bs[kk][n] ----
        #pragma unroll
        for (int i = 0; i < 2; i++) {
            int idx = tid + i * 256;
            int kk  = idx >> 5;
            int nn  = (idx & 31) << 2;
            float4 v = *reinterpret_cast<const float4*>(
                &B[(long)(k0 + kt + kk) * ldb + n0 + nn]);
            *reinterpret_cast<float4*>(&Bs[kk][nn]) = v;
        }
        __syncthreads();

        #pragma unroll
        for (int kk = 0; kk < 16; kk++) {
            float a[8], b[8];
            *reinterpret_cast<float4*>(&a[0]) = *reinterpret_cast<float4*>(&As[kk][ty * 8]);
            *reinterpret_cast<float4*>(&a[4]) = *reinterpret_cast<float4*>(&As[kk][ty * 8 + 4]);
            *reinterpret_cast<float4*>(&b[0]) = *reinterpret_cast<float4*>(&Bs[kk][tx * 8]);
            *reinterpret_cast<float4*>(&b[4]) = *reinterpret_cast<float4*>(&Bs[kk][tx * 8 + 4]);
            #pragma unroll
            for (int i = 0; i < 8; i++)
                #pragma unroll
                for (int j = 0; j < 8; j++)
                    acc[i][j] += a[i] * b[j];
        }
        __syncthreads();
    }

    #pragma unroll
    for (int i = 0; i < 8; i++) {
        long m = m0 + ty * 8 + i;
        #pragma unroll
        for (int j = 0; j < 8; j++) {
            long n = n0 + tx * 8 + j;
            if (ATOMIC) atomicAdd(&C[m * ldc + n], acc[i][j]);
            else        C[m * ldc + n] = acc[i][j];
        }
    }
}

// ---------------- small GEMM: 64x64 tile, 4x4 per thread, Kc=32 ------------
// z decomposed as b = z / HH, h = z % HH; per-operand (b, h) strides.
template<bool TA>
__global__ void __launch_bounds__(256) gemm_small(
    const float* __restrict__ Ag, const float* __restrict__ Bg, float* __restrict__ Cg,
    int K, int lda, int ldb, int ldc, int HH,
    long sAb, long sAh, long sBb, long sBh, long sCb, long sCh)
{
    int z = blockIdx.z;
    int b = z / HH;
    int h = z - b * HH;

    const float* A = Ag + b * sAb + h * sAh;
    const float* B = Bg + b * sBb + h * sBh;
    float*       C = Cg + b * sCb + h * sCh;

    int m0 = blockIdx.y * 64;
    int n0 = blockIdx.x * 64;

    __shared__ float As[32][68];    // +4 pad for NN scatter
    __shared__ float Bs[32][64];

    float acc[4][4];
    #pragma unroll
    for (int i = 0; i < 4; i++)
        #pragma unroll
        for (int j = 0; j < 4; j++) acc[i][j] = 0.f;

    int tid = threadIdx.x;
    int tx  = tid & 15;
    int ty  = tid >> 4;

    for (int kt = 0; kt < K; kt += 32) {
        if (TA) {
            #pragma unroll
            for (int i = 0; i < 2; i++) {
                int idx = tid + i * 256;           // 32 rows x 16 float4
                int kk  = idx >> 4;
                int mm  = (idx & 15) << 2;
                float4 v = *reinterpret_cast<const float4*>(
                    &A[(long)(kt + kk) * lda + m0 + mm]);
                *reinterpret_cast<float4*>(&As[kk][mm]) = v;
            }
        } else {
            #pragma unroll
            for (int i = 0; i < 2; i++) {
                int idx = tid + i * 256;           // 64 rows x 8 float4
                int mm  = idx >> 3;
                int kk  = (idx & 7) << 2;
                float4 v = *reinterpret_cast<const float4*>(
                    &A[(long)(m0 + mm) * lda + kt + kk]);
                As[kk + 0][mm] = v.x;
                As[kk + 1][mm] = v.y;
                As[kk + 2][mm] = v.z;
                As[kk + 3][mm] = v.w;
            }
        }
        #pragma unroll
        for (int i = 0; i < 2; i++) {
            int idx = tid + i * 256;
            int kk  = idx >> 4;
            int nn  = (idx & 15) << 2;
            float4 v = *reinterpret_cast<const float4*>(
                &B[(long)(kt + kk) * ldb + n0 + nn]);
            *reinterpret_cast<float4*>(&Bs[kk][nn]) = v;
        }
        __syncthreads();

        #pragma unroll
        for (int kk = 0; kk < 32; kk++) {
            float a[4], bb[4];
            *reinterpret_cast<float4*>(&a[0])  = *reinterpret_cast<float4*>(&As[kk][ty * 4]);
            *reinterpret_cast<float4*>(&bb[0]) = *reinterpret_cast<float4*>(&Bs[kk][tx * 4]);
            #pragma unroll
            for (int i = 0; i < 4; i++)
                #pragma unroll
                for (int j = 0; j < 4; j++)
                    acc[i][j] += a[i] * bb[j];
        }
        __syncthreads();
    }

    #pragma unroll
    for (int i = 0; i < 4; i++) {
        long m = m0 + ty * 4 + i;
        #pragma unroll
        for (int j = 0; j < 4; j++) {
            long n = n0 + tx * 4 + j;
            C[m * ldc + n] = acc[i][j];
        }
    }
}

// ---------------- launch ----------------------------------------------------
extern "C" void kernel_launch(void* const* d_in, const int* in_sizes, int n_in,
                              void* d_out, int out_size)
{
    (void)in_sizes; (void)n_in; (void)out_size;
    const float* x  = (const float*)d_in[0];   // (2, 4096, 512)
    const float* Wq = (const float*)d_in[1];   // (8, 512, 64)
    const float* Wk = (const float*)d_in[2];   // (8, 512, 64)
    const float* Wv = (const float*)d_in[3];   // (8, 512, 64)
    const float* Wo = (const float*)d_in[4];   // (8, 64, 512)
    float* out = (float*)d_out;                // (2, 4096, 512)

    float *pG, *pP2t, *pMt, *pR, *pWqF, *pE;
    cudaGetSymbolAddress((void**)&pG,   g_G);
    cudaGetSymbolAddress((void**)&pP2t, g_P2t);
    cudaGetSymbolAddress((void**)&pMt,  g_Mt);
    cudaGetSymbolAddress((void**)&pR,   g_R);
    cudaGetSymbolAddress((void**)&pWqF, g_WqF);
    cudaGetSymbolAddress((void**)&pE,   g_E);

    const long sX = (long)L_DIM * DIN;         // 2097152
    const long sG = (long)DIN * DIN;           // 262144
    const long sW = (long)DIN * DK;            // 32768  (also DV*DOUT)

    // 0) zero Gram (split-K accumulates atomically)
    zero_kernel<<<(B_DIM * DIN * DIN / 4 + 255) / 256, 256>>>(pG, B_DIM * DIN * DIN / 4);

    // 1) G[b] = x[b]^T x[b]   (TN, split-K=8, atomic)
    gemm_big<true, true><<<dim3(4, 4, B_DIM * 8), 256>>>(
        x, x, pG, L_DIM, DIN, DIN, DIN, sX, sX, sG, 8);

    // 2) gather Wq -> WqF[m][h*64+k]
    rearrange_wq<<<(DIN * H_DIM * DK + 255) / 256, 256>>>(Wq, pWqF);

    // 3) P2t[b,h] = G[b] @ Wk[h]     (TN via symmetry of G): M=512,N=64,K=512
    gemm_small<true><<<dim3(1, 8, B_DIM * H_DIM), 256>>>(
        pG, Wk, pP2t, DIN, DIN, DK, DK, H_DIM,
        sG, 0, 0, sW, (long)H_DIM * sW, sW);

    // 4) Mt[b,h] = (K^T V)^T = sum_k Wv[k,m] P2t[k,n]: M=64,N=64,K=512
    gemm_small<true><<<dim3(1, 1, B_DIM * H_DIM), 256>>>(
        Wv, pP2t, pMt, DIN, DK, DK, DK, H_DIM,
        0, sW, (long)H_DIM * sW, sW, (long)H_DIM * DK * DK, (long)DK * DK);

    // 5) R[b,h] = (K^T V) @ Wo[h] = sum_k Mt[k,m] Wo[k,n]: M=64,N=512,K=64
    gemm_small<true><<<dim3(8, 1, B_DIM * H_DIM), 256>>>(
        pMt, Wo, pR, DK, DK, DOUT, DOUT, H_DIM,
        (long)H_DIM * DK * DK, (long)DK * DK, 0, (long)DV * DOUT,
        (long)H_DIM * DK * DOUT, (long)DK * DOUT);

    // 6) E[b] = WqF @ R[b]   (R[b] viewed as 512x512): M=512,N=512,K=512
    gemm_small<false><<<dim3(8, 8, B_DIM), 256>>>(
        pWqF, pR, pE, H_DIM * DK, H_DIM * DK, DOUT, DOUT, 1,
        0, 0, (long)H_DIM * DK * DOUT, 0, (long)DIN * DOUT, 0);

    // 7) out[b] = x[b] @ E[b]   (NN): M=4096,N=512,K=512
    gemm_big<false, false><<<dim3(4, 32, B_DIM), 256>>>(
        x, pE, out, DIN, DIN, DOUT, DOUT, sX, (long)DIN * DOUT, sX, 1);
}